// round 6
// baseline (speedup 1.0000x reference)
#include <cuda_runtime.h>
#include <math.h>
#include <stdint.h>

#define Bb 128
#define Tt 1024
#define Ii 256
#define Hh 512
#define Vv 32000

// ---------------- scratch ----------------
__device__ float g_gates[Bb * 2048];
__device__ float g_q[Bb * Hh];
__device__ float g_scores[Bb * Tt];
__device__ float g_oin[Bb * 2 * Hh];        // [hn | context]
__device__ unsigned g_Wmp[64 * 64 * 64];    // Wm pre-permuted tf32 frags: (nt_g, ksg) -> 64 u32

__device__ __forceinline__ float fast_tanh(float x) {
    float y;
    asm("tanh.approx.f32 %0, %1;" : "=f"(y) : "f"(x));
    return y;
}
__device__ __forceinline__ float sigmoidf(float x) {
    return 1.0f / (1.0f + expf(-x));
}
__device__ __forceinline__ unsigned f2tf(float x) {
    unsigned u;
    asm("cvt.rna.tf32.f32 %0, %1;" : "=r"(u) : "f"(x));
    return u;
}
__device__ __forceinline__ void mma8(float c[4], const unsigned a[4], const unsigned b[2]) {
    asm("mma.sync.aligned.m16n8k8.row.col.f32.tf32.tf32.f32 "
        "{%0,%1,%2,%3},{%4,%5,%6,%7},{%8,%9},{%0,%1,%2,%3};"
        : "+f"(c[0]), "+f"(c[1]), "+f"(c[2]), "+f"(c[3])
        : "r"(a[0]), "r"(a[1]), "r"(a[2]), "r"(a[3]), "r"(b[0]), "r"(b[1]));
}
__device__ __forceinline__ uint32_t smem_u32(const void* p) {
    uint32_t a;
    asm("{ .reg .u64 t; cvta.to.shared.u64 t, %1; cvt.u32.u64 %0, t; }" : "=r"(a) : "l"(p));
    return a;
}
__device__ __forceinline__ void cp16(uint32_t sdst, const void* gsrc) {
    asm volatile("cp.async.cg.shared.global [%0], [%1], 16;" :: "r"(sdst), "l"(gsrc) : "memory");
}
#define CP_COMMIT() asm volatile("cp.async.commit_group;" ::: "memory")
#define CP_WAIT(n)  asm volatile("cp.async.wait_group %0;" :: "n"(n) : "memory")

#define AS 132
#define BS 66

// ---------------- prep: Wm -> tf32 fragment-ordered global copy ----------------
// frag (nt_g = n>>3, ksg = k>>3) is 64 contiguous u32; within-frag position:
// gg = n&7, kk = k&7, half = (kk>>2)&1, j = kk&3 -> pos = gg*8 + half + 2*j
__global__ __launch_bounds__(256) void wm_prep(const float* __restrict__ Wm) {
    int i = blockIdx.x * 256 + threadIdx.x;   // 0 .. 262143
    int n = i >> 9, k = i & 511;
    int nt = n >> 3, gg = n & 7, ksg = k >> 3, kk = k & 7;
    int pos = gg * 8 + ((kk >> 2) & 1) + 2 * (kk & 3);
    g_Wmp[((size_t)nt * 64 + ksg) * 64 + pos] = f2tf(Wm[(size_t)n * 512 + k]);
}

// ---------------- gates GEMM (concat-on-the-fly, SIMT tf32 mma) ----------------
__global__ __launch_bounds__(256) void gates_gemm(const float* __restrict__ x,
                                                  const float* __restrict__ op,
                                                  const float* __restrict__ hp,
                                                  const float* __restrict__ Wih,
                                                  const float* __restrict__ Whh,
                                                  const float* __restrict__ bih,
                                                  const float* __restrict__ bhh,
                                                  float* __restrict__ C) {
    __shared__ unsigned uA[32 * AS];
    __shared__ unsigned uB[32 * BS];
    int tid = threadIdx.x, lane = tid & 31, w = tid >> 5;
    int wr = w & 3, wc = w >> 2;
    int n0 = blockIdx.x * 64;
    int g = lane >> 2, t = lane & 3;

    float acc[2][4][4] = {};
    for (int k0 = 0; k0 < 1280; k0 += 32) {
#pragma unroll
        for (int it = 0; it < 4; ++it) {
            int i = tid + it * 256;
            int row = i >> 3, c = i & 7;
            int kk0 = c * 4, kk = k0 + kk0;
            float4 v;
            if (kk < 256)      v = *(const float4*)(x  + (size_t)row * 256 + kk);
            else if (kk < 768) v = *(const float4*)(op + (size_t)row * 512 + kk - 256);
            else               v = *(const float4*)(hp + (size_t)row * 512 + kk - 768);
            int mt = row >> 4, rr = row & 15, gg = rr & 7, hi = rr >> 3;
            int ks = kk0 >> 3, half = (kk0 >> 2) & 1;
            unsigned* p = &uA[(mt * 4 + ks) * AS + gg * 16 + half * 2 + hi];
            p[0] = f2tf(v.x); p[4] = f2tf(v.y); p[8] = f2tf(v.z); p[12] = f2tf(v.w);
        }
#pragma unroll
        for (int it = 0; it < 2; ++it) {
            int i = tid + it * 256;
            int n = i >> 3, c = i & 7;
            int kk0 = c * 4, kk = k0 + kk0;
            int j = n0 + n;
            float4 v = (kk < 768) ? *(const float4*)(Wih + (size_t)j * 768 + kk)
                                  : *(const float4*)(Whh + (size_t)j * 512 + kk - 768);
            int nt = n >> 3, gg = n & 7;
            int ks = kk0 >> 3, half = (kk0 >> 2) & 1;
            unsigned* p = &uB[(nt * 4 + ks) * BS + gg * 8 + half];
            p[0] = f2tf(v.x); p[2] = f2tf(v.y); p[4] = f2tf(v.z); p[6] = f2tf(v.w);
        }
        __syncthreads();
#pragma unroll
        for (int ks = 0; ks < 4; ++ks) {
            unsigned a0[4], a1[4], b[4][2];
            *(uint4*)a0 = *(const uint4*)&uA[((wr * 2 + 0) * 4 + ks) * AS + lane * 4];
            *(uint4*)a1 = *(const uint4*)&uA[((wr * 2 + 1) * 4 + ks) * AS + lane * 4];
#pragma unroll
            for (int j = 0; j < 4; ++j)
                *(uint2*)b[j] = *(const uint2*)&uB[((wc * 4 + j) * 4 + ks) * BS + lane * 2];
#pragma unroll
            for (int j = 0; j < 4; ++j) { mma8(acc[0][j], a0, b[j]); mma8(acc[1][j], a1, b[j]); }
        }
        __syncthreads();
    }
#pragma unroll
    for (int mt = 0; mt < 2; ++mt)
#pragma unroll
        for (int j = 0; j < 4; ++j)
#pragma unroll
            for (int ci = 0; ci < 4; ++ci) {
                int row = wr * 32 + mt * 16 + g + (ci >> 1) * 8;
                int col = n0 + wc * 32 + j * 8 + t * 2 + (ci & 1);
                C[(size_t)row * 2048 + col] = acc[mt][j][ci] + bih[col] + bhh[col];
            }
}

// ---------------- generic SIMT tf32 GEMM ----------------
template <int EPI>
__global__ __launch_bounds__(256) void mma_gemm(const float* __restrict__ A,
                                                const float* __restrict__ Bm,
                                                float* __restrict__ C,
                                                int N, int K) {
    __shared__ unsigned uA[32 * AS];
    __shared__ unsigned uB[32 * BS];
    int tid = threadIdx.x, lane = tid & 31, w = tid >> 5;
    int wr = w & 3, wc = w >> 2;
    int n0 = blockIdx.x * 64;
    int g = lane >> 2, t = lane & 3;

    float acc[2][4][4] = {};
    for (int k0 = 0; k0 < K; k0 += 32) {
#pragma unroll
        for (int it = 0; it < 4; ++it) {
            int i = tid + it * 256;
            int row = i >> 3, c = i & 7;
            int kk0 = c * 4;
            float4 v = *(const float4*)(A + (size_t)row * K + k0 + kk0);
            int mt = row >> 4, rr = row & 15, gg = rr & 7, hi = rr >> 3;
            int ks = kk0 >> 3, half = (kk0 >> 2) & 1;
            unsigned* p = &uA[(mt * 4 + ks) * AS + gg * 16 + half * 2 + hi];
            p[0] = f2tf(v.x); p[4] = f2tf(v.y); p[8] = f2tf(v.z); p[12] = f2tf(v.w);
        }
#pragma unroll
        for (int it = 0; it < 2; ++it) {
            int i = tid + it * 256;
            int n = i >> 3, c = i & 7;
            int kk0 = c * 4;
            float4 v = *(const float4*)(Bm + (size_t)(n0 + n) * K + k0 + kk0);
            int nt = n >> 3, gg = n & 7;
            int ks = kk0 >> 3, half = (kk0 >> 2) & 1;
            unsigned* p = &uB[(nt * 4 + ks) * BS + gg * 8 + half];
            p[0] = f2tf(v.x); p[2] = f2tf(v.y); p[4] = f2tf(v.z); p[6] = f2tf(v.w);
        }
        __syncthreads();
#pragma unroll
        for (int ks = 0; ks < 4; ++ks) {
            unsigned a0[4], a1[4], b[4][2];
            *(uint4*)a0 = *(const uint4*)&uA[((wr * 2 + 0) * 4 + ks) * AS + lane * 4];
            *(uint4*)a1 = *(const uint4*)&uA[((wr * 2 + 1) * 4 + ks) * AS + lane * 4];
#pragma unroll
            for (int j = 0; j < 4; ++j)
                *(uint2*)b[j] = *(const uint2*)&uB[((wc * 4 + j) * 4 + ks) * BS + lane * 2];
#pragma unroll
            for (int j = 0; j < 4; ++j) { mma8(acc[0][j], a0, b[j]); mma8(acc[1][j], a1, b[j]); }
        }
        __syncthreads();
    }
#pragma unroll
    for (int mt = 0; mt < 2; ++mt)
#pragma unroll
        for (int j = 0; j < 4; ++j)
#pragma unroll
            for (int ci = 0; ci < 4; ++ci) {
                int row = wr * 32 + mt * 16 + g + (ci >> 1) * 8;
                int col = n0 + wc * 32 + j * 8 + t * 2 + (ci & 1);
                float v = acc[mt][j][ci];
                if (EPI == 2) v = tanhf(v);
                C[(size_t)row * N + col] = v;
            }
}

// ---------------- fused LSTM pointwise + q = hn @ Wq^T (+ zero ctx) ----------------
__global__ __launch_bounds__(256) void lstm_q(const float* __restrict__ cp,
                                              const float* __restrict__ Wq,
                                              float* __restrict__ out_hn,
                                              float* __restrict__ out_cn) {
    int b = blockIdx.x, tid = threadIdx.x;
    __shared__ float hns[512];
    const float* g = g_gates + (size_t)b * 2048;
#pragma unroll
    for (int h = tid; h < 512; h += 256) {
        float ig = sigmoidf(g[h]);
        float fg = sigmoidf(g[512 + h]);
        float gg = tanhf(g[1024 + h]);
        float og = sigmoidf(g[1536 + h]);
        float cn = fg * cp[(size_t)b * 512 + h] + ig * gg;
        float hn = og * tanhf(cn);
        out_cn[(size_t)b * 512 + h] = cn;
        out_hn[(size_t)b * 512 + h] = hn;
        hns[h] = hn;
        g_oin[(size_t)b * 1024 + h] = hn;
        g_oin[(size_t)b * 1024 + 512 + h] = 0.0f;
    }
    __syncthreads();
#pragma unroll
    for (int n = tid; n < 512; n += 256) {
        const float4* wr = (const float4*)(Wq + (size_t)n * 512);
        float s = 0.0f;
#pragma unroll 4
        for (int i = 0; i < 128; ++i) {
            float4 v = wr[i];
            s += v.x * hns[i * 4] + v.y * hns[i * 4 + 1] + v.z * hns[i * 4 + 2] + v.w * hns[i * 4 + 3];
        }
        g_q[(size_t)b * 512 + n] = s;
    }
}

// ---------------- score kernel v5: A-resident, cp.async B from permuted Wm ----------------
// A frags contiguous: frag (mtg 0..3, ksg 0..63) = 128 u32 at ((mtg*64)+ksg)*128.
// B buffers: frag (nt 0..15, ks 0..7) = 64 u32 at (nt*8+ks)*64.  32KB per buffer.
#define SA_U32 (4 * 64 * 128)       /* 32768 u32 = 128KB */
#define SB_U32 (16 * 8 * 64)        /* 8192 u32 = 32KB per buffer */
__global__ __launch_bounds__(256, 1) void score_kernel(const float* __restrict__ enc,
                                                       const float* __restrict__ Wa) {
    extern __shared__ unsigned sm[];
    unsigned* uA  = sm;
    unsigned* uB[2] = { uA + SA_U32, uA + SA_U32 + SB_U32 };
    float* qs     = (float*)(uA + SA_U32 + 2 * SB_U32);
    float* was    = qs + 512;
    float* rowacc = was + 512;

    int tid = threadIdx.x, lane = tid & 31, w = tid >> 5;
    int wr = w & 1, wc = w >> 1;              // 2 row-warps x 4 col-warps
    int r0 = blockIdx.x * 64;
    int b = r0 >> 10;
    int g = lane >> 2, t = lane & 3;

    uint32_t b_sm[2] = { smem_u32(uB[0]), smem_u32(uB[1]) };

    for (int i = tid; i < 512; i += 256) {
        qs[i] = g_q[(size_t)b * 512 + i];
        was[i] = Wa[i];
    }
    if (tid < 64) rowacc[tid] = 0.0f;

    // ---- fill A once: 64 rows x 512 k (tf32, contiguous frag layout) ----
#pragma unroll
    for (int it = 0; it < 32; ++it) {
        int i = tid + it * 256;
        int row = i >> 7, c = i & 127;        // c = float4 index within row
        int kk0 = c * 4;
        float4 v = *(const float4*)(enc + (size_t)(r0 + row) * 512 + kk0);
        int mt = row >> 4, rr = row & 15, gg = rr & 7, hi = rr >> 3;
        int ksg = kk0 >> 3, half = (kk0 >> 2) & 1;
        unsigned* p = &uA[((mt * 64) + ksg) * 128 + gg * 16 + half * 2 + hi];
        p[0] = f2tf(v.x); p[4] = f2tf(v.y); p[8] = f2tf(v.z); p[12] = f2tf(v.w);
    }
    __syncthreads();

    for (int nc = 0; nc < 4; ++nc) {
        float acc[2][4][4] = {};
        // prologue: async-load kc=0 into buffer 0
#pragma unroll
        for (int it = 0; it < 8; ++it) {
            int c = tid + it * 256;           // 16B chunk id, 0..2047
            int f = c >> 4, wi = c & 15;      // frag 0..127, 16B-chunk within frag
            int nt = f >> 3, ks = f & 7;
            const unsigned* src = g_Wmp + (((size_t)(nc * 16 + nt) * 64) + ks) * 64 + wi * 4;
            cp16(b_sm[0] + (f * 64 + wi * 4) * 4, src);
        }
        CP_COMMIT();

        for (int kc = 0; kc < 8; ++kc) {
            unsigned* cur = uB[kc & 1];
            if (kc < 7) {
#pragma unroll
                for (int it = 0; it < 8; ++it) {
                    int c = tid + it * 256;
                    int f = c >> 4, wi = c & 15;
                    int nt = f >> 3, ks = f & 7;
                    const unsigned* src = g_Wmp + (((size_t)(nc * 16 + nt) * 64) + (kc + 1) * 8 + ks) * 64 + wi * 4;
                    cp16(b_sm[(kc + 1) & 1] + (f * 64 + wi * 4) * 4, src);
                }
                CP_COMMIT();
                CP_WAIT(1);
            } else {
                CP_WAIT(0);
            }
            __syncthreads();
#pragma unroll
            for (int ks = 0; ks < 8; ++ks) {
                int ksg = kc * 8 + ks;
                unsigned a0[4], a1[4], bf[4][2];
                *(uint4*)a0 = *(const uint4*)&uA[((wr * 2 + 0) * 64 + ksg) * 128 + lane * 4];
                *(uint4*)a1 = *(const uint4*)&uA[((wr * 2 + 1) * 64 + ksg) * 128 + lane * 4];
#pragma unroll
                for (int j = 0; j < 4; ++j)
                    *(uint2*)bf[j] = *(const uint2*)&cur[((wc * 4 + j) * 8 + ks) * 64 + lane * 2];
#pragma unroll
                for (int j = 0; j < 4; ++j) { mma8(acc[0][j], a0, bf[j]); mma8(acc[1][j], a1, bf[j]); }
            }
            __syncthreads();
        }

        // epilogue: tanh + Wa-weighted reduce over this 128-col chunk
        float p4[4] = {0.f, 0.f, 0.f, 0.f};
#pragma unroll
        for (int mt = 0; mt < 2; ++mt)
#pragma unroll
            for (int j = 0; j < 4; ++j)
#pragma unroll
                for (int ci = 0; ci < 4; ++ci) {
                    int n = nc * 128 + wc * 32 + j * 8 + t * 2 + (ci & 1);
                    p4[mt * 2 + (ci >> 1)] += was[n] * fast_tanh(acc[mt][j][ci] + qs[n]);
                }
#pragma unroll
        for (int i = 0; i < 4; ++i) {
            p4[i] += __shfl_xor_sync(0xffffffffu, p4[i], 1);
            p4[i] += __shfl_xor_sync(0xffffffffu, p4[i], 2);
        }
        if (t == 0) {
#pragma unroll
            for (int i = 0; i < 4; ++i) {
                int mt = i >> 1, h = i & 1;
                atomicAdd(&rowacc[wr * 32 + mt * 16 + g + h * 8], p4[i]);
            }
        }
    }
    __syncthreads();
    if (tid < 64) g_scores[r0 + tid] = rowacc[tid];
}

// ---------------- softmax over T ----------------
__global__ __launch_bounds__(256) void softmax_t(float* __restrict__ out_w) {
    int b = blockIdx.x, tid = threadIdx.x;
    __shared__ float red[256];
    const float* s = g_scores + (size_t)b * 1024;
    float v0 = s[tid], v1 = s[tid + 256], v2 = s[tid + 512], v3 = s[tid + 768];
    float lmax = fmaxf(fmaxf(v0, v1), fmaxf(v2, v3));
    red[tid] = lmax; __syncthreads();
    for (int st = 128; st > 0; st >>= 1) {
        if (tid < st) red[tid] = fmaxf(red[tid], red[tid + st]);
        __syncthreads();
    }
    float m = red[0];
    __syncthreads();
    float e0 = expf(v0 - m), e1 = expf(v1 - m), e2 = expf(v2 - m), e3 = expf(v3 - m);
    red[tid] = e0 + e1 + e2 + e3; __syncthreads();
    for (int st = 128; st > 0; st >>= 1) {
        if (tid < st) red[tid] += red[tid + st];
        __syncthreads();
    }
    float inv = 1.0f / red[0];
    float* w = out_w + (size_t)b * 1024;
    w[tid] = e0 * inv; w[tid + 256] = e1 * inv;
    w[tid + 512] = e2 * inv; w[tid + 768] = e3 * inv;
}

// ---------------- context partial ----------------
__global__ __launch_bounds__(256) void ctx_partial(const float* __restrict__ enc,
                                                   const float* __restrict__ wgt) {
    int b = blockIdx.x, ch = blockIdx.y, tid = threadIdx.x;
    __shared__ float w[128];
    if (tid < 128) w[tid] = wgt[(size_t)b * 1024 + ch * 128 + tid];
    __syncthreads();

    int h0 = tid * 2;
    float c0 = 0.0f, c1 = 0.0f;
    const float* eb = enc + (size_t)b * 1024 * 512 + (size_t)ch * 128 * 512;
#pragma unroll 4
    for (int t = 0; t < 128; ++t) {
        float2 e = *(const float2*)(eb + (size_t)t * 512 + h0);
        float wt = w[t];
        c0 += wt * e.x;
        c1 += wt * e.y;
    }
    atomicAdd(&g_oin[(size_t)b * 1024 + 512 + h0], c0);
    atomicAdd(&g_oin[(size_t)b * 1024 + 512 + h0 + 1], c1);
}

// ---------------- log_softmax over V ----------------
__global__ __launch_bounds__(1024) void logsm(float* __restrict__ out) {
    int b = blockIdx.x, tid = threadIdx.x;
    __shared__ float red[1024];
    float* row = out + (size_t)b * Vv;

    float lmax = -1e30f;
    for (int i = tid; i < Vv; i += 1024) lmax = fmaxf(lmax, row[i]);
    red[tid] = lmax; __syncthreads();
    for (int s = 512; s > 0; s >>= 1) {
        if (tid < s) red[tid] = fmaxf(red[tid], red[tid + s]);
        __syncthreads();
    }
    float m = red[0];
    __syncthreads();

    float lsum = 0.0f;
    for (int i = tid; i < Vv; i += 1024) lsum += expf(row[i] - m);
    red[tid] = lsum; __syncthreads();
    for (int s = 512; s > 0; s >>= 1) {
        if (tid < s) red[tid] += red[tid + s];
        __syncthreads();
    }
    float lse = m + logf(red[0]);
    __syncthreads();

    for (int i = tid; i < Vv; i += 1024) row[i] -= lse;
}

// ---------------- launch ----------------
extern "C" void kernel_launch(void* const* d_in, const int* in_sizes, int n_in,
                              void* d_out, int out_size) {
    const float* x    = (const float*)d_in[0];
    const float* hp   = (const float*)d_in[1];
    const float* cp   = (const float*)d_in[2];
    const float* op   = (const float*)d_in[3];
    const float* enc  = (const float*)d_in[4];
    const float* Wih  = (const float*)d_in[5];
    const float* Whh  = (const float*)d_in[6];
    const float* bih  = (const float*)d_in[7];
    const float* bhh  = (const float*)d_in[8];
    const float* Wq   = (const float*)d_in[9];
    const float* Wm   = (const float*)d_in[10];
    const float* Wa   = (const float*)d_in[11];
    const float* Wo   = (const float*)d_in[12];
    const float* Wout = (const float*)d_in[13];

    float* out        = (float*)d_out;
    float* out_logits = out;
    float* out_hn     = out + (size_t)Bb * Vv;
    float* out_cn     = out_hn + Bb * Hh;
    float* out_on     = out_cn + Bb * Hh;
    float* out_w      = out_on + Bb * Hh;

    float *pgates, *poin;
    cudaGetSymbolAddress((void**)&pgates, g_gates);
    cudaGetSymbolAddress((void**)&poin,  g_oin);

    size_t score_smem = (size_t)(SA_U32 + 2 * SB_U32 + 512 + 512 + 64) * 4;
    cudaFuncSetAttribute(score_kernel, cudaFuncAttributeMaxDynamicSharedMemorySize,
                         (int)score_smem);

    // 0. pre-permute Wm to tf32 frag order
    wm_prep<<<1024, 256>>>(Wm);
    // 1. gates = [x|op|hp] @ [Wih|Whh]^T + bias
    gates_gemm<<<32, 256>>>(x, op, hp, Wih, Whh, bih, bhh, pgates);
    // 2. LSTM pointwise + q (+ zero ctx accumulator)
    lstm_q<<<128, 256>>>(cp, Wq, out_hn, out_cn);
    // 3. fused scores (cp.async pipelined B)
    score_kernel<<<2048, 256, score_smem>>>(enc, Wa);
    // 4. softmax over T
    softmax_t<<<128, 256>>>(out_w);
    // 5. context
    ctx_partial<<<dim3(128, 8), 256>>>(enc, out_w);
    // 6. on = tanh(o_in @ Wo^T)
    mma_gemm<2><<<8, 256>>>(poin, Wo, out_on, 512, 1024);
    // 7. logits = on @ Wout^T
    mma_gemm<0><<<500, 256>>>(out_on, Wout, out_logits, 32000, 512);
    // 8. log_softmax in place
    logsm<<<128, 1024>>>(out_logits);
}

// round 7
// speedup vs baseline: 1.0709x; 1.0709x over previous
#include <cuda_runtime.h>
#include <math.h>
#include <stdint.h>

#define Bb 128
#define Tt 1024
#define Ii 256
#define Hh 512
#define Vv 32000

// ---------------- scratch ----------------
__device__ float g_gates[Bb * 2048];
__device__ float g_q[Bb * Hh];
__device__ float g_scores[Bb * Tt];
__device__ float g_oin[Bb * 2 * Hh];        // [hn | context]
__device__ unsigned g_Wmp[64 * 64 * 64];    // Wm tf32 frags: (nt, ksg) -> 64 u32

__device__ __forceinline__ float fast_tanh(float x) {
    float y;
    asm("tanh.approx.f32 %0, %1;" : "=f"(y) : "f"(x));
    return y;
}
__device__ __forceinline__ float sigmoidf(float x) {
    return 1.0f / (1.0f + expf(-x));
}
__device__ __forceinline__ unsigned f2tf(float x) {
    unsigned u;
    asm("cvt.rna.tf32.f32 %0, %1;" : "=r"(u) : "f"(x));
    return u;
}
__device__ __forceinline__ void mma8(float c[4], const unsigned a[4], const unsigned b[2]) {
    asm("mma.sync.aligned.m16n8k8.row.col.f32.tf32.tf32.f32 "
        "{%0,%1,%2,%3},{%4,%5,%6,%7},{%8,%9},{%0,%1,%2,%3};"
        : "+f"(c[0]), "+f"(c[1]), "+f"(c[2]), "+f"(c[3])
        : "r"(a[0]), "r"(a[1]), "r"(a[2]), "r"(a[3]), "r"(b[0]), "r"(b[1]));
}
__device__ __forceinline__ uint32_t smem_u32(const void* p) {
    uint32_t a;
    asm("{ .reg .u64 t; cvta.to.shared.u64 t, %1; cvt.u32.u64 %0, t; }" : "=r"(a) : "l"(p));
    return a;
}
__device__ __forceinline__ void cp16(uint32_t sdst, const void* gsrc) {
    asm volatile("cp.async.cg.shared.global [%0], [%1], 16;" :: "r"(sdst), "l"(gsrc) : "memory");
}
#define CP_COMMIT() asm volatile("cp.async.commit_group;" ::: "memory")
#define CP_WAIT(n)  asm volatile("cp.async.wait_group %0;" :: "n"(n) : "memory")

#define AS 132
#define BS 66

// ---------------- prep: Wm -> tf32 fragment-ordered global copy ----------------
__global__ __launch_bounds__(256) void wm_prep(const float* __restrict__ Wm) {
    int i = blockIdx.x * 256 + threadIdx.x;   // 0 .. 262143
    int n = i >> 9, k = i & 511;
    int nt = n >> 3, gg = n & 7, ksg = k >> 3, kk = k & 7;
    int pos = gg * 8 + ((kk >> 2) & 1) + 2 * (kk & 3);
    g_Wmp[((size_t)nt * 64 + ksg) * 64 + pos] = f2tf(Wm[(size_t)n * 512 + k]);
}

// ---------------- gates GEMM (concat-on-the-fly, SIMT tf32 mma) ----------------
__global__ __launch_bounds__(256) void gates_gemm(const float* __restrict__ x,
                                                  const float* __restrict__ op,
                                                  const float* __restrict__ hp,
                                                  const float* __restrict__ Wih,
                                                  const float* __restrict__ Whh,
                                                  const float* __restrict__ bih,
                                                  const float* __restrict__ bhh,
                                                  float* __restrict__ C) {
    __shared__ unsigned uA[32 * AS];
    __shared__ unsigned uB[32 * BS];
    int tid = threadIdx.x, lane = tid & 31, w = tid >> 5;
    int wr = w & 3, wc = w >> 2;
    int n0 = blockIdx.x * 64;
    int g = lane >> 2, t = lane & 3;

    float acc[2][4][4] = {};
    for (int k0 = 0; k0 < 1280; k0 += 32) {
#pragma unroll
        for (int it = 0; it < 4; ++it) {
            int i = tid + it * 256;
            int row = i >> 3, c = i & 7;
            int kk0 = c * 4, kk = k0 + kk0;
            float4 v;
            if (kk < 256)      v = *(const float4*)(x  + (size_t)row * 256 + kk);
            else if (kk < 768) v = *(const float4*)(op + (size_t)row * 512 + kk - 256);
            else               v = *(const float4*)(hp + (size_t)row * 512 + kk - 768);
            int mt = row >> 4, rr = row & 15, gg = rr & 7, hi = rr >> 3;
            int ks = kk0 >> 3, half = (kk0 >> 2) & 1;
            unsigned* p = &uA[(mt * 4 + ks) * AS + gg * 16 + half * 2 + hi];
            p[0] = f2tf(v.x); p[4] = f2tf(v.y); p[8] = f2tf(v.z); p[12] = f2tf(v.w);
        }
#pragma unroll
        for (int it = 0; it < 2; ++it) {
            int i = tid + it * 256;
            int n = i >> 3, c = i & 7;
            int kk0 = c * 4, kk = k0 + kk0;
            int j = n0 + n;
            float4 v = (kk < 768) ? *(const float4*)(Wih + (size_t)j * 768 + kk)
                                  : *(const float4*)(Whh + (size_t)j * 512 + kk - 768);
            int nt = n >> 3, gg = n & 7;
            int ks = kk0 >> 3, half = (kk0 >> 2) & 1;
            unsigned* p = &uB[(nt * 4 + ks) * BS + gg * 8 + half];
            p[0] = f2tf(v.x); p[2] = f2tf(v.y); p[4] = f2tf(v.z); p[6] = f2tf(v.w);
        }
        __syncthreads();
#pragma unroll
        for (int ks = 0; ks < 4; ++ks) {
            unsigned a0[4], a1[4], b[4][2];
            *(uint4*)a0 = *(const uint4*)&uA[((wr * 2 + 0) * 4 + ks) * AS + lane * 4];
            *(uint4*)a1 = *(const uint4*)&uA[((wr * 2 + 1) * 4 + ks) * AS + lane * 4];
#pragma unroll
            for (int j = 0; j < 4; ++j)
                *(uint2*)b[j] = *(const uint2*)&uB[((wc * 4 + j) * 4 + ks) * BS + lane * 2];
#pragma unroll
            for (int j = 0; j < 4; ++j) { mma8(acc[0][j], a0, b[j]); mma8(acc[1][j], a1, b[j]); }
        }
        __syncthreads();
    }
#pragma unroll
    for (int mt = 0; mt < 2; ++mt)
#pragma unroll
        for (int j = 0; j < 4; ++j)
#pragma unroll
            for (int ci = 0; ci < 4; ++ci) {
                int row = wr * 32 + mt * 16 + g + (ci >> 1) * 8;
                int col = n0 + wc * 32 + j * 8 + t * 2 + (ci & 1);
                C[(size_t)row * 2048 + col] = acc[mt][j][ci] + bih[col] + bhh[col];
            }
}

// ---------------- generic SIMT tf32 GEMM ----------------
template <int EPI>
__global__ __launch_bounds__(256) void mma_gemm(const float* __restrict__ A,
                                                const float* __restrict__ Bm,
                                                float* __restrict__ C,
                                                int N, int K) {
    __shared__ unsigned uA[32 * AS];
    __shared__ unsigned uB[32 * BS];
    int tid = threadIdx.x, lane = tid & 31, w = tid >> 5;
    int wr = w & 3, wc = w >> 2;
    int n0 = blockIdx.x * 64;
    int g = lane >> 2, t = lane & 3;

    float acc[2][4][4] = {};
    for (int k0 = 0; k0 < K; k0 += 32) {
#pragma unroll
        for (int it = 0; it < 4; ++it) {
            int i = tid + it * 256;
            int row = i >> 3, c = i & 7;
            int kk0 = c * 4;
            float4 v = *(const float4*)(A + (size_t)row * K + k0 + kk0);
            int mt = row >> 4, rr = row & 15, gg = rr & 7, hi = rr >> 3;
            int ks = kk0 >> 3, half = (kk0 >> 2) & 1;
            unsigned* p = &uA[(mt * 4 + ks) * AS + gg * 16 + half * 2 + hi];
            p[0] = f2tf(v.x); p[4] = f2tf(v.y); p[8] = f2tf(v.z); p[12] = f2tf(v.w);
        }
#pragma unroll
        for (int it = 0; it < 2; ++it) {
            int i = tid + it * 256;
            int n = i >> 3, c = i & 7;
            int kk0 = c * 4;
            float4 v = *(const float4*)(Bm + (size_t)(n0 + n) * K + k0 + kk0);
            int nt = n >> 3, gg = n & 7;
            int ks = kk0 >> 3, half = (kk0 >> 2) & 1;
            unsigned* p = &uB[(nt * 4 + ks) * BS + gg * 8 + half];
            p[0] = f2tf(v.x); p[2] = f2tf(v.y); p[4] = f2tf(v.z); p[6] = f2tf(v.w);
        }
        __syncthreads();
#pragma unroll
        for (int ks = 0; ks < 4; ++ks) {
            unsigned a0[4], a1[4], b[4][2];
            *(uint4*)a0 = *(const uint4*)&uA[((wr * 2 + 0) * 4 + ks) * AS + lane * 4];
            *(uint4*)a1 = *(const uint4*)&uA[((wr * 2 + 1) * 4 + ks) * AS + lane * 4];
#pragma unroll
            for (int j = 0; j < 4; ++j)
                *(uint2*)b[j] = *(const uint2*)&uB[((wc * 4 + j) * 4 + ks) * BS + lane * 2];
#pragma unroll
            for (int j = 0; j < 4; ++j) { mma8(acc[0][j], a0, b[j]); mma8(acc[1][j], a1, b[j]); }
        }
        __syncthreads();
    }
#pragma unroll
    for (int mt = 0; mt < 2; ++mt)
#pragma unroll
        for (int j = 0; j < 4; ++j)
#pragma unroll
            for (int ci = 0; ci < 4; ++ci) {
                int row = wr * 32 + mt * 16 + g + (ci >> 1) * 8;
                int col = n0 + wc * 32 + j * 8 + t * 2 + (ci & 1);
                float v = acc[mt][j][ci];
                if (EPI == 2) v = tanhf(v);
                C[(size_t)row * N + col] = v;
            }
}

// ---------------- fused LSTM pointwise + q = hn @ Wq^T (+ zero ctx) ----------------
__global__ __launch_bounds__(256) void lstm_q(const float* __restrict__ cp,
                                              const float* __restrict__ Wq,
                                              float* __restrict__ out_hn,
                                              float* __restrict__ out_cn) {
    int b = blockIdx.x, tid = threadIdx.x;
    __shared__ float hns[512];
    const float* g = g_gates + (size_t)b * 2048;
#pragma unroll
    for (int h = tid; h < 512; h += 256) {
        float ig = sigmoidf(g[h]);
        float fg = sigmoidf(g[512 + h]);
        float gg = tanhf(g[1024 + h]);
        float og = sigmoidf(g[1536 + h]);
        float cn = fg * cp[(size_t)b * 512 + h] + ig * gg;
        float hn = og * tanhf(cn);
        out_cn[(size_t)b * 512 + h] = cn;
        out_hn[(size_t)b * 512 + h] = hn;
        hns[h] = hn;
        g_oin[(size_t)b * 1024 + h] = hn;
        g_oin[(size_t)b * 1024 + 512 + h] = 0.0f;
    }
    __syncthreads();
#pragma unroll
    for (int n = tid; n < 512; n += 256) {
        const float4* wr = (const float4*)(Wq + (size_t)n * 512);
        float s = 0.0f;
#pragma unroll 4
        for (int i = 0; i < 128; ++i) {
            float4 v = wr[i];
            s += v.x * hns[i * 4] + v.y * hns[i * 4 + 1] + v.z * hns[i * 4 + 2] + v.w * hns[i * 4 + 3];
        }
        g_q[(size_t)b * 512 + n] = s;
    }
}

// ---------------- score kernel v6: warp tile 64x64, full-N, cp.async B ring ----------------
// A resident: frag (mt 0..3, ksg 0..63) = 128 u32 at (mt*64+ksg)*128.   128KB
// B ring: 2 slices; slice = 2 ksg x 64 nt; frag (nt, kslot) at (nt*2+kslot)*64. 32KB each
#define SA_U32 (4 * 64 * 128)
#define SB_U32 (64 * 2 * 64)
__global__ __launch_bounds__(256, 1) void score_kernel(const float* __restrict__ enc,
                                                       const float* __restrict__ Wa) {
    extern __shared__ unsigned sm[];
    unsigned* uA  = sm;
    unsigned* uB[2] = { uA + SA_U32, uA + SA_U32 + SB_U32 };
    float* qs     = (float*)(uA + SA_U32 + 2 * SB_U32);
    float* was    = qs + 512;
    float* rowacc = was + 512;

    int tid = threadIdx.x, lane = tid & 31, w = tid >> 5;
    int r0 = blockIdx.x * 64;
    int b = r0 >> 10;
    int g = lane >> 2, t = lane & 3;

    uint32_t b_sm[2] = { smem_u32(uB[0]), smem_u32(uB[1]) };

    for (int i = tid; i < 512; i += 256) {
        qs[i] = g_q[(size_t)b * 512 + i];
        was[i] = Wa[i];
    }
    if (tid < 64) rowacc[tid] = 0.0f;

    // ---- fill A once: 64 rows x 512 k ----
#pragma unroll
    for (int it = 0; it < 32; ++it) {
        int i = tid + it * 256;
        int row = i >> 7, c = i & 127;
        int kk0 = c * 4;
        float4 v = *(const float4*)(enc + (size_t)(r0 + row) * 512 + kk0);
        int mt = row >> 4, rr = row & 15, gg = rr & 7, hi = rr >> 3;
        int ksg = kk0 >> 3, half = (kk0 >> 2) & 1;
        unsigned* p = &uA[((mt * 64) + ksg) * 128 + gg * 16 + half * 2 + hi];
        p[0] = f2tf(v.x); p[4] = f2tf(v.y); p[8] = f2tf(v.z); p[12] = f2tf(v.w);
    }

    float acc[4][8][4] = {};

    // prologue: load slice 0 (ksg 0,1) into buf 0
#pragma unroll
    for (int it = 0; it < 8; ++it) {
        int c = tid + it * 256;               // 16B chunk, 0..2047
        int f = c >> 4, wi = c & 15;          // f: (nt, kslot) pair 0..127
        int nt = f >> 1, kslot = f & 1;
        const unsigned* src = g_Wmp + (((size_t)nt * 64) + kslot) * 64 + wi * 4;
        cp16(b_sm[0] + (f * 64 + wi * 4) * 4, src);
    }
    CP_COMMIT();

    for (int itk = 0; itk < 32; ++itk) {
        unsigned* cur = uB[itk & 1];
        if (itk < 31) {
#pragma unroll
            for (int it = 0; it < 8; ++it) {
                int c = tid + it * 256;
                int f = c >> 4, wi = c & 15;
                int nt = f >> 1, kslot = f & 1;
                const unsigned* src = g_Wmp + (((size_t)nt * 64) + 2 * (itk + 1) + kslot) * 64 + wi * 4;
                cp16(b_sm[(itk + 1) & 1] + (f * 64 + wi * 4) * 4, src);
            }
            CP_COMMIT();
            CP_WAIT(1);
        } else {
            CP_WAIT(0);
        }
        __syncthreads();
#pragma unroll
        for (int kslot = 0; kslot < 2; ++kslot) {
            int ksg = itk * 2 + kslot;
            unsigned a[4][4], bf[8][2];
#pragma unroll
            for (int mt = 0; mt < 4; ++mt)
                *(uint4*)a[mt] = *(const uint4*)&uA[((mt * 64) + ksg) * 128 + lane * 4];
#pragma unroll
            for (int j = 0; j < 8; ++j)
                *(uint2*)bf[j] = *(const uint2*)&cur[(((w * 8 + j) * 2) + kslot) * 64 + lane * 2];
#pragma unroll
            for (int mt = 0; mt < 4; ++mt)
#pragma unroll
                for (int j = 0; j < 8; ++j)
                    mma8(acc[mt][j], a[mt], bf[j]);
        }
        __syncthreads();
    }

    // epilogue: warp w covers cols [w*64, w*64+64); reduce tanh*Wa over cols
    float pr[8] = {0.f, 0.f, 0.f, 0.f, 0.f, 0.f, 0.f, 0.f};
#pragma unroll
    for (int mt = 0; mt < 4; ++mt)
#pragma unroll
        for (int j = 0; j < 8; ++j)
#pragma unroll
            for (int ci = 0; ci < 4; ++ci) {
                int n = w * 64 + j * 8 + t * 2 + (ci & 1);
                pr[mt * 2 + (ci >> 1)] += was[n] * fast_tanh(acc[mt][j][ci] + qs[n]);
            }
#pragma unroll
    for (int i = 0; i < 8; ++i) {
        pr[i] += __shfl_xor_sync(0xffffffffu, pr[i], 1);
        pr[i] += __shfl_xor_sync(0xffffffffu, pr[i], 2);
    }
    if (t == 0) {
#pragma unroll
        for (int i = 0; i < 8; ++i) {
            int mt = i >> 1, h = i & 1;
            atomicAdd(&rowacc[mt * 16 + g + h * 8], pr[i]);
        }
    }
    __syncthreads();
    if (tid < 64) g_scores[r0 + tid] = rowacc[tid];
}

// ---------------- softmax over T ----------------
__global__ __launch_bounds__(256) void softmax_t(float* __restrict__ out_w) {
    int b = blockIdx.x, tid = threadIdx.x;
    __shared__ float red[256];
    const float* s = g_scores + (size_t)b * 1024;
    float v0 = s[tid], v1 = s[tid + 256], v2 = s[tid + 512], v3 = s[tid + 768];
    float lmax = fmaxf(fmaxf(v0, v1), fmaxf(v2, v3));
    red[tid] = lmax; __syncthreads();
    for (int st = 128; st > 0; st >>= 1) {
        if (tid < st) red[tid] = fmaxf(red[tid], red[tid + st]);
        __syncthreads();
    }
    float m = red[0];
    __syncthreads();
    float e0 = expf(v0 - m), e1 = expf(v1 - m), e2 = expf(v2 - m), e3 = expf(v3 - m);
    red[tid] = e0 + e1 + e2 + e3; __syncthreads();
    for (int st = 128; st > 0; st >>= 1) {
        if (tid < st) red[tid] += red[tid + st];
        __syncthreads();
    }
    float inv = 1.0f / red[0];
    float* w = out_w + (size_t)b * 1024;
    w[tid] = e0 * inv; w[tid + 256] = e1 * inv;
    w[tid + 512] = e2 * inv; w[tid + 768] = e3 * inv;
}

// ---------------- context partial ----------------
__global__ __launch_bounds__(256) void ctx_partial(const float* __restrict__ enc,
                                                   const float* __restrict__ wgt) {
    int b = blockIdx.x, ch = blockIdx.y, tid = threadIdx.x;
    __shared__ float w[128];
    if (tid < 128) w[tid] = wgt[(size_t)b * 1024 + ch * 128 + tid];
    __syncthreads();

    int h0 = tid * 2;
    float c0 = 0.0f, c1 = 0.0f;
    const float* eb = enc + (size_t)b * 1024 * 512 + (size_t)ch * 128 * 512;
#pragma unroll 4
    for (int t = 0; t < 128; ++t) {
        float2 e = *(const float2*)(eb + (size_t)t * 512 + h0);
        float wt = w[t];
        c0 += wt * e.x;
        c1 += wt * e.y;
    }
    atomicAdd(&g_oin[(size_t)b * 1024 + 512 + h0], c0);
    atomicAdd(&g_oin[(size_t)b * 1024 + 512 + h0 + 1], c1);
}

// ---------------- log_softmax over V ----------------
__global__ __launch_bounds__(1024) void logsm(float* __restrict__ out) {
    int b = blockIdx.x, tid = threadIdx.x;
    __shared__ float red[1024];
    float* row = out + (size_t)b * Vv;

    float lmax = -1e30f;
    for (int i = tid; i < Vv; i += 1024) lmax = fmaxf(lmax, row[i]);
    red[tid] = lmax; __syncthreads();
    for (int s = 512; s > 0; s >>= 1) {
        if (tid < s) red[tid] = fmaxf(red[tid], red[tid + s]);
        __syncthreads();
    }
    float m = red[0];
    __syncthreads();

    float lsum = 0.0f;
    for (int i = tid; i < Vv; i += 1024) lsum += expf(row[i] - m);
    red[tid] = lsum; __syncthreads();
    for (int s = 512; s > 0; s >>= 1) {
        if (tid < s) red[tid] += red[tid + s];
        __syncthreads();
    }
    float lse = m + logf(red[0]);
    __syncthreads();

    for (int i = tid; i < Vv; i += 1024) row[i] -= lse;
}

// ---------------- launch ----------------
extern "C" void kernel_launch(void* const* d_in, const int* in_sizes, int n_in,
                              void* d_out, int out_size) {
    const float* x    = (const float*)d_in[0];
    const float* hp   = (const float*)d_in[1];
    const float* cp   = (const float*)d_in[2];
    const float* op   = (const float*)d_in[3];
    const float* enc  = (const float*)d_in[4];
    const float* Wih  = (const float*)d_in[5];
    const float* Whh  = (const float*)d_in[6];
    const float* bih  = (const float*)d_in[7];
    const float* bhh  = (const float*)d_in[8];
    const float* Wq   = (const float*)d_in[9];
    const float* Wm   = (const float*)d_in[10];
    const float* Wa   = (const float*)d_in[11];
    const float* Wo   = (const float*)d_in[12];
    const float* Wout = (const float*)d_in[13];

    float* out        = (float*)d_out;
    float* out_logits = out;
    float* out_hn     = out + (size_t)Bb * Vv;
    float* out_cn     = out_hn + Bb * Hh;
    float* out_on     = out_cn + Bb * Hh;
    float* out_w      = out_on + Bb * Hh;

    float *pgates, *poin;
    cudaGetSymbolAddress((void**)&pgates, g_gates);
    cudaGetSymbolAddress((void**)&poin,  g_oin);

    size_t score_smem = (size_t)(SA_U32 + 2 * SB_U32 + 512 + 512 + 64) * 4;
    cudaFuncSetAttribute(score_kernel, cudaFuncAttributeMaxDynamicSharedMemorySize,
                         (int)score_smem);

    // 0. pre-permute Wm to tf32 frag order
    wm_prep<<<1024, 256>>>(Wm);
    // 1. gates = [x|op|hp] @ [Wih|Whh]^T + bias
    gates_gemm<<<32, 256>>>(x, op, hp, Wih, Whh, bih, bhh, pgates);
    // 2. LSTM pointwise + q (+ zero ctx accumulator)
    lstm_q<<<128, 256>>>(cp, Wq, out_hn, out_cn);
    // 3. fused scores (warp tile 64x64, cp.async B ring)
    score_kernel<<<2048, 256, score_smem>>>(enc, Wa);
    // 4. softmax over T
    softmax_t<<<128, 256>>>(out_w);
    // 5. context
    ctx_partial<<<dim3(128, 8), 256>>>(enc, out_w);
    // 6. on = tanh(o_in @ Wo^T)
    mma_gemm<2><<<8, 256>>>(poin, Wo, out_on, 512, 1024);
    // 7. logits = on @ Wout^T
    mma_gemm<0><<<500, 256>>>(out_on, Wout, out_logits, 32000, 512);
    // 8. log_softmax in place
    logsm<<<128, 1024>>>(out_logits);
}

// round 8
// speedup vs baseline: 1.5712x; 1.4671x over previous
#include <cuda_runtime.h>
#include <cuda_fp16.h>
#include <math.h>
#include <stdint.h>

#define Bb 128
#define Tt 1024
#define Ii 256
#define Hh 512
#define Vv 32000

// ---------------- scratch ----------------
__device__ float g_gates[Bb * 2048];
__device__ float g_q[Bb * Hh];
__device__ float g_scores[Bb * Tt];
__device__ float g_oin[Bb * 2 * Hh];           // [hn | context]
__device__ __half g_Wmph[64 * 32 * 128];       // Wm fp16 frags: (nt, ksg16) -> 128 halves

__device__ __forceinline__ float fast_tanh(float x) {
    float y;
    asm("tanh.approx.f32 %0, %1;" : "=f"(y) : "f"(x));
    return y;
}
__device__ __forceinline__ float sigmoidf(float x) {
    return 1.0f / (1.0f + expf(-x));
}
__device__ __forceinline__ unsigned f2tf(float x) {
    unsigned u;
    asm("cvt.rna.tf32.f32 %0, %1;" : "=r"(u) : "f"(x));
    return u;
}
__device__ __forceinline__ void mma8(float c[4], const unsigned a[4], const unsigned b[2]) {
    asm("mma.sync.aligned.m16n8k8.row.col.f32.tf32.tf32.f32 "
        "{%0,%1,%2,%3},{%4,%5,%6,%7},{%8,%9},{%0,%1,%2,%3};"
        : "+f"(c[0]), "+f"(c[1]), "+f"(c[2]), "+f"(c[3])
        : "r"(a[0]), "r"(a[1]), "r"(a[2]), "r"(a[3]), "r"(b[0]), "r"(b[1]));
}
__device__ __forceinline__ void mma16(float c[4], const unsigned a[4], const unsigned b[2]) {
    asm("mma.sync.aligned.m16n8k16.row.col.f32.f16.f16.f32 "
        "{%0,%1,%2,%3},{%4,%5,%6,%7},{%8,%9},{%0,%1,%2,%3};"
        : "+f"(c[0]), "+f"(c[1]), "+f"(c[2]), "+f"(c[3])
        : "r"(a[0]), "r"(a[1]), "r"(a[2]), "r"(a[3]), "r"(b[0]), "r"(b[1]));
}
__device__ __forceinline__ uint32_t smem_u32(const void* p) {
    uint32_t a;
    asm("{ .reg .u64 t; cvta.to.shared.u64 t, %1; cvt.u32.u64 %0, t; }" : "=r"(a) : "l"(p));
    return a;
}
__device__ __forceinline__ void cp16(uint32_t sdst, const void* gsrc) {
    asm volatile("cp.async.cg.shared.global [%0], [%1], 16;" :: "r"(sdst), "l"(gsrc) : "memory");
}
#define CP_COMMIT() asm volatile("cp.async.commit_group;" ::: "memory")
#define CP_WAIT(n)  asm volatile("cp.async.wait_group %0;" :: "n"(n) : "memory")

#define AS 132
#define BS 66

// ---------------- prep: Wm -> fp16 fragment-ordered (m16n8k16 B-frag) ----------------
// B[k][n] = Wm[n][k]. frag (nt = n>>3, ksg16 = k>>4) = 128 halves.
// element: gg=n&7, kk=k&15: t=(kk&7)>>1, r=kk>>3, e=kk&1 -> half idx = (8*gg+2*t+r)*2 + e
__global__ __launch_bounds__(256) void wm_prep(const float* __restrict__ Wm) {
    int i = blockIdx.x * 256 + threadIdx.x;    // 0 .. 262143
    int n = i >> 9, k = i & 511;
    int nt = n >> 3, gg = n & 7, ksg = k >> 4, kk = k & 15;
    int t = (kk & 7) >> 1, r = kk >> 3, e = kk & 1;
    g_Wmph[((size_t)nt * 32 + ksg) * 128 + (8 * gg + 2 * t + r) * 2 + e] =
        __float2half_rn(Wm[(size_t)n * 512 + k]);
}

// ---------------- gates GEMM (concat-on-the-fly, SIMT tf32 mma) ----------------
__global__ __launch_bounds__(256) void gates_gemm(const float* __restrict__ x,
                                                  const float* __restrict__ op,
                                                  const float* __restrict__ hp,
                                                  const float* __restrict__ Wih,
                                                  const float* __restrict__ Whh,
                                                  const float* __restrict__ bih,
                                                  const float* __restrict__ bhh,
                                                  float* __restrict__ C) {
    __shared__ unsigned uA[32 * AS];
    __shared__ unsigned uB[32 * BS];
    int tid = threadIdx.x, lane = tid & 31, w = tid >> 5;
    int wr = w & 3, wc = w >> 2;
    int n0 = blockIdx.x * 64;
    int g = lane >> 2, t = lane & 3;

    float acc[2][4][4] = {};
    for (int k0 = 0; k0 < 1280; k0 += 32) {
#pragma unroll
        for (int it = 0; it < 4; ++it) {
            int i = tid + it * 256;
            int row = i >> 3, c = i & 7;
            int kk0 = c * 4, kk = k0 + kk0;
            float4 v;
            if (kk < 256)      v = *(const float4*)(x  + (size_t)row * 256 + kk);
            else if (kk < 768) v = *(const float4*)(op + (size_t)row * 512 + kk - 256);
            else               v = *(const float4*)(hp + (size_t)row * 512 + kk - 768);
            int mt = row >> 4, rr = row & 15, gg = rr & 7, hi = rr >> 3;
            int ks = kk0 >> 3, half = (kk0 >> 2) & 1;
            unsigned* p = &uA[(mt * 4 + ks) * AS + gg * 16 + half * 2 + hi];
            p[0] = f2tf(v.x); p[4] = f2tf(v.y); p[8] = f2tf(v.z); p[12] = f2tf(v.w);
        }
#pragma unroll
        for (int it = 0; it < 2; ++it) {
            int i = tid + it * 256;
            int n = i >> 3, c = i & 7;
            int kk0 = c * 4, kk = k0 + kk0;
            int j = n0 + n;
            float4 v = (kk < 768) ? *(const float4*)(Wih + (size_t)j * 768 + kk)
                                  : *(const float4*)(Whh + (size_t)j * 512 + kk - 768);
            int nt = n >> 3, gg = n & 7;
            int ks = kk0 >> 3, half = (kk0 >> 2) & 1;
            unsigned* p = &uB[(nt * 4 + ks) * BS + gg * 8 + half];
            p[0] = f2tf(v.x); p[2] = f2tf(v.y); p[4] = f2tf(v.z); p[6] = f2tf(v.w);
        }
        __syncthreads();
#pragma unroll
        for (int ks = 0; ks < 4; ++ks) {
            unsigned a0[4], a1[4], b[4][2];
            *(uint4*)a0 = *(const uint4*)&uA[((wr * 2 + 0) * 4 + ks) * AS + lane * 4];
            *(uint4*)a1 = *(const uint4*)&uA[((wr * 2 + 1) * 4 + ks) * AS + lane * 4];
#pragma unroll
            for (int j = 0; j < 4; ++j)
                *(uint2*)b[j] = *(const uint2*)&uB[((wc * 4 + j) * 4 + ks) * BS + lane * 2];
#pragma unroll
            for (int j = 0; j < 4; ++j) { mma8(acc[0][j], a0, b[j]); mma8(acc[1][j], a1, b[j]); }
        }
        __syncthreads();
    }
#pragma unroll
    for (int mt = 0; mt < 2; ++mt)
#pragma unroll
        for (int j = 0; j < 4; ++j)
#pragma unroll
            for (int ci = 0; ci < 4; ++ci) {
                int row = wr * 32 + mt * 16 + g + (ci >> 1) * 8;
                int col = n0 + wc * 32 + j * 8 + t * 2 + (ci & 1);
                C[(size_t)row * 2048 + col] = acc[mt][j][ci] + bih[col] + bhh[col];
            }
}

// ---------------- generic SIMT tf32 GEMM ----------------
template <int EPI>
__global__ __launch_bounds__(256) void mma_gemm(const float* __restrict__ A,
                                                const float* __restrict__ Bm,
                                                float* __restrict__ C,
                                                int N, int K) {
    __shared__ unsigned uA[32 * AS];
    __shared__ unsigned uB[32 * BS];
    int tid = threadIdx.x, lane = tid & 31, w = tid >> 5;
    int wr = w & 3, wc = w >> 2;
    int n0 = blockIdx.x * 64;
    int g = lane >> 2, t = lane & 3;

    float acc[2][4][4] = {};
    for (int k0 = 0; k0 < K; k0 += 32) {
#pragma unroll
        for (int it = 0; it < 4; ++it) {
            int i = tid + it * 256;
            int row = i >> 3, c = i & 7;
            int kk0 = c * 4;
            float4 v = *(const float4*)(A + (size_t)row * K + k0 + kk0);
            int mt = row >> 4, rr = row & 15, gg = rr & 7, hi = rr >> 3;
            int ks = kk0 >> 3, half = (kk0 >> 2) & 1;
            unsigned* p = &uA[(mt * 4 + ks) * AS + gg * 16 + half * 2 + hi];
            p[0] = f2tf(v.x); p[4] = f2tf(v.y); p[8] = f2tf(v.z); p[12] = f2tf(v.w);
        }
#pragma unroll
        for (int it = 0; it < 2; ++it) {
            int i = tid + it * 256;
            int n = i >> 3, c = i & 7;
            int kk0 = c * 4;
            float4 v = *(const float4*)(Bm + (size_t)(n0 + n) * K + k0 + kk0);
            int nt = n >> 3, gg = n & 7;
            int ks = kk0 >> 3, half = (kk0 >> 2) & 1;
            unsigned* p = &uB[(nt * 4 + ks) * BS + gg * 8 + half];
            p[0] = f2tf(v.x); p[2] = f2tf(v.y); p[4] = f2tf(v.z); p[6] = f2tf(v.w);
        }
        __syncthreads();
#pragma unroll
        for (int ks = 0; ks < 4; ++ks) {
            unsigned a0[4], a1[4], b[4][2];
            *(uint4*)a0 = *(const uint4*)&uA[((wr * 2 + 0) * 4 + ks) * AS + lane * 4];
            *(uint4*)a1 = *(const uint4*)&uA[((wr * 2 + 1) * 4 + ks) * AS + lane * 4];
#pragma unroll
            for (int j = 0; j < 4; ++j)
                *(uint2*)b[j] = *(const uint2*)&uB[((wc * 4 + j) * 4 + ks) * BS + lane * 2];
#pragma unroll
            for (int j = 0; j < 4; ++j) { mma8(acc[0][j], a0, b[j]); mma8(acc[1][j], a1, b[j]); }
        }
        __syncthreads();
    }
#pragma unroll
    for (int mt = 0; mt < 2; ++mt)
#pragma unroll
        for (int j = 0; j < 4; ++j)
#pragma unroll
            for (int ci = 0; ci < 4; ++ci) {
                int row = wr * 32 + mt * 16 + g + (ci >> 1) * 8;
                int col = n0 + wc * 32 + j * 8 + t * 2 + (ci & 1);
                float v = acc[mt][j][ci];
                if (EPI == 2) v = tanhf(v);
                C[(size_t)row * N + col] = v;
            }
}

// ---------------- fused LSTM pointwise + q = hn @ Wq^T (+ zero ctx) ----------------
__global__ __launch_bounds__(256) void lstm_q(const float* __restrict__ cp,
                                              const float* __restrict__ Wq,
                                              float* __restrict__ out_hn,
                                              float* __restrict__ out_cn) {
    int b = blockIdx.x, tid = threadIdx.x;
    __shared__ float hns[512];
    const float* g = g_gates + (size_t)b * 2048;
#pragma unroll
    for (int h = tid; h < 512; h += 256) {
        float ig = sigmoidf(g[h]);
        float fg = sigmoidf(g[512 + h]);
        float gg = tanhf(g[1024 + h]);
        float og = sigmoidf(g[1536 + h]);
        float cn = fg * cp[(size_t)b * 512 + h] + ig * gg;
        float hn = og * tanhf(cn);
        out_cn[(size_t)b * 512 + h] = cn;
        out_hn[(size_t)b * 512 + h] = hn;
        hns[h] = hn;
        g_oin[(size_t)b * 1024 + h] = hn;
        g_oin[(size_t)b * 1024 + 512 + h] = 0.0f;
    }
    __syncthreads();
#pragma unroll
    for (int n = tid; n < 512; n += 256) {
        const float4* wr = (const float4*)(Wq + (size_t)n * 512);
        float s = 0.0f;
#pragma unroll 4
        for (int i = 0; i < 128; ++i) {
            float4 v = wr[i];
            s += v.x * hns[i * 4] + v.y * hns[i * 4 + 1] + v.z * hns[i * 4 + 2] + v.w * hns[i * 4 + 3];
        }
        g_q[(size_t)b * 512 + n] = s;
    }
}

// ---------------- score kernel v7: fp16 m16n8k16, warp tile 64x64, cp.async B ring ----
// A resident fp16: frag (mt 0..3, ksg16 0..31) = 128 u32 at (mt*32+ksg16)*128.  64KB
// B ring: 2 buffers; buffer = 2 kslots x 64 nt; frag (nt,kslot) at (nt*2+kslot)*64. 32KB each
#define SA_U32 (4 * 32 * 128)
#define SB_U32 (64 * 2 * 64)
__global__ __launch_bounds__(256, 1) void score_kernel(const float* __restrict__ enc,
                                                       const float* __restrict__ Wa) {
    extern __shared__ unsigned sm[];
    unsigned* uA  = sm;
    unsigned* uB[2] = { uA + SA_U32, uA + SA_U32 + SB_U32 };
    float* qs     = (float*)(uA + SA_U32 + 2 * SB_U32);
    float* was    = qs + 512;
    float* rowacc = was + 512;

    int tid = threadIdx.x, lane = tid & 31, w = tid >> 5;
    int r0 = blockIdx.x * 64;
    int b = r0 >> 10;
    int g = lane >> 2, t = lane & 3;

    uint32_t b_sm[2] = { smem_u32(uB[0]), smem_u32(uB[1]) };

    for (int i = tid; i < 512; i += 256) {
        qs[i] = g_q[(size_t)b * 512 + i];
        was[i] = Wa[i];
    }
    if (tid < 64) rowacc[tid] = 0.0f;

    // ---- fill A once: 64 rows x 512 k, converted to fp16 m16n8k16 A-frag layout ----
    // element (row,k): g=row&7(within 16), hi=row bit3, t=(k&7)>>1, s=k>>3(within 16), e=k&1
    // u32 pos in frag = 16*g + 4*t + (hi + 2*s); halves packed (e=0 low, e=1 high)
#pragma unroll
    for (int it = 0; it < 32; ++it) {
        int i = tid + it * 256;
        int row = i >> 7, c = i & 127;
        int k0 = c * 4;
        float4 v = *(const float4*)(enc + (size_t)(r0 + row) * 512 + k0);
        int mt = row >> 4, rr = row & 15, gg = rr & 7, hi = rr >> 3;
        int ksg = k0 >> 4, kk = k0 & 15;
        int t0 = (kk & 7) >> 1, s = kk >> 3;
        unsigned* base = &uA[((mt * 32) + ksg) * 128];
        int pos = 16 * gg + 4 * t0 + hi + 2 * s;
        __half2 lo = __floats2half2_rn(v.x, v.y);
        __half2 hi2 = __floats2half2_rn(v.z, v.w);
        base[pos]     = *(unsigned*)&lo;
        base[pos + 4] = *(unsigned*)&hi2;
    }

    float acc[4][8][4] = {};

    // prologue: load slice 0 (ksg16 0,1) into buf 0
#pragma unroll
    for (int it = 0; it < 8; ++it) {
        int c = tid + it * 256;               // 16B chunk, 0..2047
        int f = c >> 4, wi = c & 15;          // f = nt*2 + kslot
        int nt = f >> 1, kslot = f & 1;
        const __half* src = g_Wmph + (((size_t)nt * 32) + kslot) * 128 + wi * 8;
        cp16(b_sm[0] + (f * 64 + wi * 4) * 4, src);
    }
    CP_COMMIT();

    for (int itk = 0; itk < 16; ++itk) {
        unsigned* cur = uB[itk & 1];
        if (itk < 15) {
#pragma unroll
            for (int it = 0; it < 8; ++it) {
                int c = tid + it * 256;
                int f = c >> 4, wi = c & 15;
                int nt = f >> 1, kslot = f & 1;
                const __half* src = g_Wmph + (((size_t)nt * 32) + 2 * (itk + 1) + kslot) * 128 + wi * 8;
                cp16(b_sm[(itk + 1) & 1] + (f * 64 + wi * 4) * 4, src);
            }
            CP_COMMIT();
            CP_WAIT(1);
        } else {
            CP_WAIT(0);
        }
        __syncthreads();
#pragma unroll
        for (int kslot = 0; kslot < 2; ++kslot) {
            int ksg = itk * 2 + kslot;
            unsigned a[4][4], bf[8][2];
#pragma unroll
            for (int mt = 0; mt < 4; ++mt)
                *(uint4*)a[mt] = *(const uint4*)&uA[((mt * 32) + ksg) * 128 + lane * 4];
#pragma unroll
            for (int j = 0; j < 8; ++j)
                *(uint2*)bf[j] = *(const uint2*)&cur[(((w * 8 + j) * 2) + kslot) * 64 + lane * 2];
#pragma unroll
            for (int mt = 0; mt < 4; ++mt)
#pragma unroll
                for (int j = 0; j < 8; ++j)
                    mma16(acc[mt][j], a[mt], bf[j]);
        }
        __syncthreads();
    }

    // epilogue: warp w covers cols [w*64, w*64+64); reduce tanh*Wa over cols
    float pr[8] = {0.f, 0.f, 0.f, 0.f, 0.f, 0.f, 0.f, 0.f};
#pragma unroll
    for (int mt = 0; mt < 4; ++mt)
#pragma unroll
        for (int j = 0; j < 8; ++j)
#pragma unroll
            for (int ci = 0; ci < 4; ++ci) {
                int n = w * 64 + j * 8 + t * 2 + (ci & 1);
                pr[mt * 2 + (ci >> 1)] += was[n] * fast_tanh(acc[mt][j][ci] + qs[n]);
            }
#pragma unroll
    for (int i = 0; i < 8; ++i) {
        pr[i] += __shfl_xor_sync(0xffffffffu, pr[i], 1);
        pr[i] += __shfl_xor_sync(0xffffffffu, pr[i], 2);
    }
    if (t == 0) {
#pragma unroll
        for (int i = 0; i < 8; ++i) {
            int mt = i >> 1, h = i & 1;
            atomicAdd(&rowacc[mt * 16 + g + h * 8], pr[i]);
        }
    }
    __syncthreads();
    if (tid < 64) g_scores[r0 + tid] = rowacc[tid];
}

// ---------------- softmax over T ----------------
__global__ __launch_bounds__(256) void softmax_t(float* __restrict__ out_w) {
    int b = blockIdx.x, tid = threadIdx.x;
    __shared__ float red[256];
    const float* s = g_scores + (size_t)b * 1024;
    float v0 = s[tid], v1 = s[tid + 256], v2 = s[tid + 512], v3 = s[tid + 768];
    float lmax = fmaxf(fmaxf(v0, v1), fmaxf(v2, v3));
    red[tid] = lmax; __syncthreads();
    for (int st = 128; st > 0; st >>= 1) {
        if (tid < st) red[tid] = fmaxf(red[tid], red[tid + st]);
        __syncthreads();
    }
    float m = red[0];
    __syncthreads();
    float e0 = expf(v0 - m), e1 = expf(v1 - m), e2 = expf(v2 - m), e3 = expf(v3 - m);
    red[tid] = e0 + e1 + e2 + e3; __syncthreads();
    for (int st = 128; st > 0; st >>= 1) {
        if (tid < st) red[tid] += red[tid + st];
        __syncthreads();
    }
    float inv = 1.0f / red[0];
    float* w = out_w + (size_t)b * 1024;
    w[tid] = e0 * inv; w[tid + 256] = e1 * inv;
    w[tid + 512] = e2 * inv; w[tid + 768] = e3 * inv;
}

// ---------------- context partial ----------------
__global__ __launch_bounds__(256) void ctx_partial(const float* __restrict__ enc,
                                                   const float* __restrict__ wgt) {
    int b = blockIdx.x, ch = blockIdx.y, tid = threadIdx.x;
    __shared__ float w[128];
    if (tid < 128) w[tid] = wgt[(size_t)b * 1024 + ch * 128 + tid];
    __syncthreads();

    int h0 = tid * 2;
    float c0 = 0.0f, c1 = 0.0f;
    const float* eb = enc + (size_t)b * 1024 * 512 + (size_t)ch * 128 * 512;
#pragma unroll 4
    for (int t = 0; t < 128; ++t) {
        float2 e = *(const float2*)(eb + (size_t)t * 512 + h0);
        float wt = w[t];
        c0 += wt * e.x;
        c1 += wt * e.y;
    }
    atomicAdd(&g_oin[(size_t)b * 1024 + 512 + h0], c0);
    atomicAdd(&g_oin[(size_t)b * 1024 + 512 + h0 + 1], c1);
}

// ---------------- log_softmax over V ----------------
__global__ __launch_bounds__(1024) void logsm(float* __restrict__ out) {
    int b = blockIdx.x, tid = threadIdx.x;
    __shared__ float red[1024];
    float* row = out + (size_t)b * Vv;

    float lmax = -1e30f;
    for (int i = tid; i < Vv; i += 1024) lmax = fmaxf(lmax, row[i]);
    red[tid] = lmax; __syncthreads();
    for (int s = 512; s > 0; s >>= 1) {
        if (tid < s) red[tid] = fmaxf(red[tid], red[tid + s]);
        __syncthreads();
    }
    float m = red[0];
    __syncthreads();

    float lsum = 0.0f;
    for (int i = tid; i < Vv; i += 1024) lsum += expf(row[i] - m);
    red[tid] = lsum; __syncthreads();
    for (int s = 512; s > 0; s >>= 1) {
        if (tid < s) red[tid] += red[tid + s];
        __syncthreads();
    }
    float lse = m + logf(red[0]);
    __syncthreads();

    for (int i = tid; i < Vv; i += 1024) row[i] -= lse;
}

// ---------------- launch ----------------
extern "C" void kernel_launch(void* const* d_in, const int* in_sizes, int n_in,
                              void* d_out, int out_size) {
    const float* x    = (const float*)d_in[0];
    const float* hp   = (const float*)d_in[1];
    const float* cp   = (const float*)d_in[2];
    const float* op   = (const float*)d_in[3];
    const float* enc  = (const float*)d_in[4];
    const float* Wih  = (const float*)d_in[5];
    const float* Whh  = (const float*)d_in[6];
    const float* bih  = (const float*)d_in[7];
    const float* bhh  = (const float*)d_in[8];
    const float* Wq   = (const float*)d_in[9];
    const float* Wm   = (const float*)d_in[10];
    const float* Wa   = (const float*)d_in[11];
    const float* Wo   = (const float*)d_in[12];
    const float* Wout = (const float*)d_in[13];

    float* out        = (float*)d_out;
    float* out_logits = out;
    float* out_hn     = out + (size_t)Bb * Vv;
    float* out_cn     = out_hn + Bb * Hh;
    float* out_on     = out_cn + Bb * Hh;
    float* out_w      = out_on + Bb * Hh;

    float *pgates, *poin;
    cudaGetSymbolAddress((void**)&pgates, g_gates);
    cudaGetSymbolAddress((void**)&poin,  g_oin);

    size_t score_smem = (size_t)(SA_U32 + 2 * SB_U32 + 512 + 512 + 64) * 4;
    cudaFuncSetAttribute(score_kernel, cudaFuncAttributeMaxDynamicSharedMemorySize,
                         (int)score_smem);

    // 0. pre-permute Wm to fp16 frag order
    wm_prep<<<1024, 256>>>(Wm);
    // 1. gates = [x|op|hp] @ [Wih|Whh]^T + bias
    gates_gemm<<<32, 256>>>(x, op, hp, Wih, Whh, bih, bhh, pgates);
    // 2. LSTM pointwise + q (+ zero ctx accumulator)
    lstm_q<<<128, 256>>>(cp, Wq, out_hn, out_cn);
    // 3. fused scores (fp16 m16n8k16, warp tile 64x64, cp.async B ring)
    score_kernel<<<2048, 256, score_smem>>>(enc, Wa);
    // 4. softmax over T
    softmax_t<<<128, 256>>>(out_w);
    // 5. context
    ctx_partial<<<dim3(128, 8), 256>>>(enc, out_w);
    // 6. on = tanh(o_in @ Wo^T)
    mma_gemm<2><<<8, 256>>>(poin, Wo, out_on, 512, 1024);
    // 7. logits = on @ Wout^T
    mma_gemm<0><<<500, 256>>>(out_on, Wout, out_logits, 32000, 512);
    // 8. log_softmax in place
    logsm<<<128, 1024>>>(out_logits);
}